// round 12
// baseline (speedup 1.0000x reference)
#include <cuda_runtime.h>
#include <math.h>

#define NTOK 100
#define OTM  25
#define MP   26
#define QP   18
#define YP   33
#define NTHREADS 128

// smem layout (float units), 9284 floats = 37136 B
#define OFF_W    0        // wbuf[2704]; after decoder: YbG rows 0..118 (row=i+8), 119*33=3927
#define OFF_QKV  3952     // QKV[100][18]=1800; after transformer: otw[800], Pd[32]@+800
#define OFF_KM   5752     // KmG[122][26]=3172 (row=i+8); vlist aliases during transformer
#define OFF_UU   8924     // uuG[124] (idx=i+8)
#define OFF_WU   9048     // wu[100]
#define OFF_VV   9148     // vv[32] ([25..31]=0)
#define OFF_AA   9180     // aaArr[100]
#define OFF_NV   9280
#define OFF_CNT  9281
#define OFF_FLG  9282
#define SMEM_FLOATS 9284
#define SMEM_BYTES  (SMEM_FLOATS * 4)

__global__ void __launch_bounds__(NTHREADS, 4)
jc_struc_kernel(const float* __restrict__ jc,   const int* __restrict__ flg,
                const float* __restrict__ enc_w, const float* __restrict__ enc_b,
                const float* __restrict__ B_sig, const float* __restrict__ B_jid,
                const float* __restrict__ qkv_w, const float* __restrict__ out_w,
                const float* __restrict__ out_b, const float* __restrict__ ln1_s,
                const float* __restrict__ ln1_b, const float* __restrict__ ln2_s,
                const float* __restrict__ ln2_b, const float* __restrict__ ff1_w,
                const float* __restrict__ ff1_b, const float* __restrict__ ff2_w,
                const float* __restrict__ ff2_b, const float* __restrict__ dec_w,
                const float* __restrict__ dec_b, const float* __restrict__ ot_w,
                float* __restrict__ out)
{
    extern __shared__ float sm[];
    float* wbuf  = sm + OFF_W;
    float* YbG   = sm + OFF_W;                 // row = i+8, pitch 33
    float* SQ    = sm + OFF_QKV;
    float* otw   = sm + OFF_QKV;
    float* Pd    = sm + OFF_QKV + 800;
    float* KmG   = sm + OFF_KM;                // row = i+8, pitch 26
    int*   vlist = (int*)(sm + OFF_KM);
    float* uuG   = sm + OFF_UU;                // idx = i+8
    float* wu    = sm + OFF_WU;
    float* vv    = sm + OFF_VV;
    float* aaArr = sm + OFF_AA;
    int*   nvp   = (int*)(sm + OFF_NV);
    float* cntp  = sm + OFF_CNT;
    int*   flagp = (int*)(sm + OFF_FLG);

    const int tid  = threadIdx.x;
    const int lane = tid & 31;
    const int s    = blockIdx.x;
    const int t    = tid;
    const float TWO_PI = 6.283185307179586f;
    const float INV_SQRT2 = 0.7071067811865476f;
    const float INV100 = 0.00999999977648258209228515625f; // fl32(1/100)
    const float INV25  = 0.039999999105930328369140625f;   // fl32(1/25)

    float x[64];

    // ================= Stage embedding constants, then embed =================
    for (int i = tid; i < 384; i += NTHREADS) {
        float v;
        if (i < 96)       v = B_sig[i];
        else if (i < 128) v = B_jid[i - 96];
        else if (i < 320) v = enc_w[i - 128];
        else              v = enc_b[i - 320];
        wbuf[i] = v;
    }
    __syncthreads();
    if (t < NTOK) {
        const size_t base = ((size_t)s * NTOK + t) * 3;
        const float p0 = jc[base + 0], p1 = jc[base + 1], p2 = jc[base + 2];
        const float jd = (float)(t / 4);
        aaArr[t] = (flg[(size_t)s * NTOK + t] > 0) ? 1.0f : 0.0f;
        const float* bs = wbuf;
        const float* bj = wbuf + 96;
        const float* ew = wbuf + 128;
        const float* eb = wbuf + 320;
        #pragma unroll 4
        for (int c = 0; c < 32; c++) {
            float proj = TWO_PI * (p0 * bs[c] + p1 * bs[32 + c] + p2 * bs[64 + c]);
            float ss, cs; __sincosf(proj, &ss, &cs);
            float pj = TWO_PI * (jd * bj[c]);
            float sj, cj; __sincosf(pj, &sj, &cj);
            x[c]      = (p0 * ew[c]      + p1 * ew[64 + c]      + p2 * ew[128 + c])      + eb[c]      + ss + sj;
            x[c + 32] = (p0 * ew[c + 32] + p1 * ew[64 + c + 32] + p2 * ew[128 + c + 32]) + eb[c + 32] + cs + cj;
        }
    }
    __syncthreads();
    if (tid == 0) {
        int c = 0;
        for (int i = 0; i < NTOK; i++) {
            if (aaArr[i] != 0.0f) vlist[c++] = i;
        }
        *nvp = c;
        *cntp = 1.0f / (float)c;
    }
    __syncthreads();
    const int nv = *nvp;

    // ================= Transformer layers =================
    #pragma unroll 1
    for (int l = 0; l < 4; l++) {
        // Phase A: ln1_s@0, ln1_b@64, qkv padded [64][20] @128
        for (int i = tid; i < 1408; i += NTHREADS) {
            float v;
            if (i < 64)       v = ln1_s[l * 64 + i];
            else if (i < 128) v = ln1_b[l * 64 + (i - 64)];
            else {
                int k = (i - 128) / 20, c = (i - 128) % 20;
                v = (c < 18) ? qkv_w[(l * 64 + k) * 18 + c] : 0.0f;
            }
            wbuf[i] = v;
        }
        __syncthreads();

        // LN1 (regs) + QKV matmul (float4 weights, scalar FMA)
        if (t < NTOK) {
            float ssum = 0.f, sq = 0.f;
            #pragma unroll
            for (int d = 0; d < 64; d++) { float v = x[d]; ssum += v; sq += v * v; }
            float mu = ssum * (1.0f / 64.0f);
            float rs = rsqrtf(sq * (1.0f / 64.0f) - mu * mu + 1e-5f);

            float acc[18];
            #pragma unroll
            for (int c = 0; c < 18; c++) acc[c] = 0.f;
            #pragma unroll
            for (int k = 0; k < 64; k++) {
                float h = fmaf((x[k] - mu) * rs, wbuf[k], wbuf[64 + k]);
                const float4* wr = (const float4*)&wbuf[128 + k * 20];
                float4 w0 = wr[0], w1 = wr[1], w2 = wr[2], w3 = wr[3], w4 = wr[4];
                acc[0] += h * w0.x;  acc[1] += h * w0.y;  acc[2] += h * w0.z;  acc[3] += h * w0.w;
                acc[4] += h * w1.x;  acc[5] += h * w1.y;  acc[6] += h * w1.z;  acc[7] += h * w1.w;
                acc[8] += h * w2.x;  acc[9] += h * w2.y;  acc[10] += h * w2.z; acc[11] += h * w2.w;
                acc[12] += h * w3.x; acc[13] += h * w3.y; acc[14] += h * w3.z; acc[15] += h * w3.w;
                acc[16] += h * w4.x; acc[17] += h * w4.y;
            }
            float* q = &SQ[t * QP];
            *(float2*)(q + 0)  = make_float2(acc[0], acc[1]);
            *(float2*)(q + 2)  = make_float2(acc[2], acc[3]);
            *(float2*)(q + 4)  = make_float2(acc[4], acc[5]);
            *(float2*)(q + 6)  = make_float2(acc[6] * INV_SQRT2, acc[7] * INV_SQRT2);
            *(float2*)(q + 8)  = make_float2(acc[8] * INV_SQRT2, acc[9] * INV_SQRT2);
            *(float2*)(q + 10) = make_float2(acc[10] * INV_SQRT2, acc[11] * INV_SQRT2);
            *(float2*)(q + 12) = make_float2(acc[12], acc[13]);
            *(float2*)(q + 14) = make_float2(acc[14], acc[15]);
            *(float2*)(q + 16) = make_float2(acc[16], acc[17]);
        }
        __syncthreads();

        // Phase B+C weights — loaded by the 28 idle threads, in the shadow of attention
        if (t >= NTOK) {
            for (int i = t - NTOK; i < 576; i += 28) {
                float v;
                if (i < 384)      v = out_w[l * 384 + i];
                else if (i < 448) v = out_b[l * 64 + (i - 384)];
                else if (i < 512) v = ln2_s[l * 64 + (i - 448)];
                else              v = ln2_b[l * 64 + (i - 512)];
                wbuf[i] = v;
            }
            for (int i = t - NTOK; i < 256; i += 28)
                ((float4*)&wbuf[576])[i] = ((const float4*)&ff1_w[l * 1024])[i];
            for (int i = t - NTOK; i < 16; i += 28)
                wbuf[1600 + i] = ff1_b[l * 16 + i];
            for (int i = t - NTOK; i < 256; i += 28)
                ((float4*)&wbuf[1616])[i] = ((const float4*)&ff2_w[l * 1024])[i];
            for (int i = t - NTOK; i < 64; i += 28)
                wbuf[2640 + i] = ff2_b[l * 64 + i];
        }

        // Attention: online softmax over compacted valid keys
        float o[6];
        if (t < NTOK) {
            const float* qp = &SQ[t * QP];
            float q0 = qp[0], q1 = qp[1], q2 = qp[2], q3 = qp[3], q4 = qp[4], q5 = qp[5];
            float m0 = -3.0e38f, m1 = -3.0e38f, m2 = -3.0e38f;
            float d0 = 0.f, d1 = 0.f, d2 = 0.f;
            float a0 = 0.f, a1 = 0.f, a2 = 0.f, a3 = 0.f, a4 = 0.f, a5 = 0.f;
            for (int jj = 0; jj < nv; jj++) {
                int j = vlist[jj];
                const float* kj = &SQ[j * QP];
                float2 k01 = *(const float2*)(kj + 6);
                float2 k23 = *(const float2*)(kj + 8);
                float2 k45 = *(const float2*)(kj + 10);
                float2 v01 = *(const float2*)(kj + 12);
                float2 v23 = *(const float2*)(kj + 14);
                float2 v45 = *(const float2*)(kj + 16);
                float s0 = q0 * k01.x + q1 * k01.y;
                float s1 = q2 * k23.x + q3 * k23.y;
                float s2 = q4 * k45.x + q5 * k45.y;
                if (s0 <= m0 && s1 <= m1 && s2 <= m2) {
                    float e0 = __expf(s0 - m0), e1 = __expf(s1 - m1), e2 = __expf(s2 - m2);
                    d0 += e0; a0 += e0 * v01.x; a1 += e0 * v01.y;
                    d1 += e1; a2 += e1 * v23.x; a3 += e1 * v23.y;
                    d2 += e2; a4 += e2 * v45.x; a5 += e2 * v45.y;
                } else {
                    float n0 = fmaxf(m0, s0), r0 = __expf(m0 - n0), e0 = __expf(s0 - n0);
                    d0 = d0 * r0 + e0; a0 = a0 * r0 + e0 * v01.x; a1 = a1 * r0 + e0 * v01.y; m0 = n0;
                    float n1 = fmaxf(m1, s1), r1 = __expf(m1 - n1), e1 = __expf(s1 - n1);
                    d1 = d1 * r1 + e1; a2 = a2 * r1 + e1 * v23.x; a3 = a3 * r1 + e1 * v23.y; m1 = n1;
                    float n2 = fmaxf(m2, s2), r2 = __expf(m2 - n2), e2 = __expf(s2 - n2);
                    d2 = d2 * r2 + e2; a4 = a4 * r2 + e2 * v45.x; a5 = a5 * r2 + e2 * v45.y; m2 = n2;
                }
            }
            o[0] = a0 / d0; o[1] = a1 / d0;
            o[2] = a2 / d1; o[3] = a3 / d1;
            o[4] = a4 / d2; o[5] = a5 / d2;
        }
        __syncthreads();

        if (t < NTOK) {
            // out projection + residual
            #pragma unroll
            for (int eh = 0; eh < 4; eh++) {
                const int e0 = eh * 16;
                float acc[16];
                const float4* bb = (const float4*)&wbuf[384 + e0];
                #pragma unroll
                for (int i = 0; i < 4; i++) {
                    float4 b4 = bb[i];
                    acc[4*i] = b4.x; acc[4*i+1] = b4.y; acc[4*i+2] = b4.z; acc[4*i+3] = b4.w;
                }
                #pragma unroll
                for (int c = 0; c < 6; c++) {
                    float oc = o[c];
                    const float4* wr = (const float4*)&wbuf[c * 64 + e0];
                    #pragma unroll
                    for (int i = 0; i < 4; i++) {
                        float4 w4 = wr[i];
                        acc[4*i]   += oc * w4.x; acc[4*i+1] += oc * w4.y;
                        acc[4*i+2] += oc * w4.z; acc[4*i+3] += oc * w4.w;
                    }
                }
                #pragma unroll
                for (int i = 0; i < 16; i++) x[e0 + i] += acc[i];
            }
            // LN2 stats
            float ssum = 0.f, sq = 0.f;
            #pragma unroll
            for (int d = 0; d < 64; d++) { float v = x[d]; ssum += v; sq += v * v; }
            float mu = ssum * (1.0f / 64.0f);
            float rs = rsqrtf(sq * (1.0f / 64.0f) - mu * mu + 1e-5f);
            // FF1 (LN2 inline)
            float g[16];
            {
                const float4* bb = (const float4*)&wbuf[1600];
                #pragma unroll
                for (int i = 0; i < 4; i++) {
                    float4 b4 = bb[i];
                    g[4*i] = b4.x; g[4*i+1] = b4.y; g[4*i+2] = b4.z; g[4*i+3] = b4.w;
                }
            }
            #pragma unroll
            for (int k = 0; k < 64; k++) {
                float h = fmaf((x[k] - mu) * rs, wbuf[448 + k], wbuf[512 + k]);
                const float4* wr = (const float4*)&wbuf[576 + k * 16];
                float4 w0 = wr[0], w1 = wr[1], w2 = wr[2], w3 = wr[3];
                g[0] += h * w0.x;  g[1] += h * w0.y;  g[2] += h * w0.z;  g[3] += h * w0.w;
                g[4] += h * w1.x;  g[5] += h * w1.y;  g[6] += h * w1.z;  g[7] += h * w1.w;
                g[8] += h * w2.x;  g[9] += h * w2.y;  g[10] += h * w2.z; g[11] += h * w2.w;
                g[12] += h * w3.x; g[13] += h * w3.y; g[14] += h * w3.z; g[15] += h * w3.w;
            }
            #pragma unroll
            for (int c = 0; c < 16; c++)
                g[c] = 0.5f * g[c] * (1.0f + erff(g[c] * INV_SQRT2));
            // FF2 + residual
            #pragma unroll
            for (int eh = 0; eh < 4; eh++) {
                const int e0 = eh * 16;
                float acc[16];
                const float4* bb = (const float4*)&wbuf[2640 + e0];
                #pragma unroll
                for (int i = 0; i < 4; i++) {
                    float4 b4 = bb[i];
                    acc[4*i] = b4.x; acc[4*i+1] = b4.y; acc[4*i+2] = b4.z; acc[4*i+3] = b4.w;
                }
                #pragma unroll
                for (int c = 0; c < 16; c++) {
                    float gc = g[c];
                    const float4* wr = (const float4*)&wbuf[1616 + c * 64 + e0];
                    #pragma unroll
                    for (int i = 0; i < 4; i++) {
                        float4 w4 = wr[i];
                        acc[4*i]   += gc * w4.x; acc[4*i+1] += gc * w4.y;
                        acc[4*i+2] += gc * w4.z; acc[4*i+3] += gc * w4.w;
                    }
                }
                #pragma unroll
                for (int i = 0; i < 16; i++) x[e0 + i] += acc[i];
            }
        }
        __syncthreads();
    }

    // ================= Decoder weights + otw =================
    for (int i = tid; i < 512; i += NTHREADS)
        ((float4*)&wbuf[0])[i] = ((const float4*)dec_w)[i];
    for (int i = tid; i < 32; i += NTHREADS)
        wbuf[2048 + i] = dec_b[i];
    for (int i = tid; i < 200; i += NTHREADS)
        ((float4*)otw)[i] = ((const float4*)ot_w)[i];
    __syncthreads();

    // ================= Decoder -> y regs =================
    float y[32];
    if (t < NTOK) {
        const float4* bb = (const float4*)&wbuf[2048];
        #pragma unroll
        for (int i = 0; i < 8; i++) {
            float4 b4 = bb[i];
            y[4*i] = b4.x; y[4*i+1] = b4.y; y[4*i+2] = b4.z; y[4*i+3] = b4.w;
        }
        #pragma unroll
        for (int k = 0; k < 64; k++) {
            float xv = x[k];
            const float4* wr = (const float4*)&wbuf[k * 32];
            #pragma unroll
            for (int i = 0; i < 8; i++) {
                float4 w4 = wr[i];
                y[4*i]   += xv * w4.x; y[4*i+1] += xv * w4.y;
                y[4*i+2] += xv * w4.z; y[4*i+3] += xv * w4.w;
            }
        }
        #pragma unroll
        for (int c = 0; c < 32; c++) y[c] = fmaxf(y[c], 0.f);
    }
    __syncthreads();        // decoder-weight reads done; YbG may overwrite wbuf
    if (t < NTOK) {
        #pragma unroll
        for (int c = 0; c < 32; c++) YbG[(t + 8) * YP + c] = y[c];
    }
    // zero guard rows of YbG (rows 0..7, 108..118) and uuG guards
    for (int i = tid; i < 264; i += NTHREADS) YbG[i] = 0.f;
    for (int i = tid; i < 363; i += NTHREADS) YbG[108 * YP + i] = 0.f;
    if (tid < 8) uuG[tid] = 0.f;
    if (tid >= 108 && tid < 124) uuG[tid] = 0.f;

    // ================= K-build: band window, exact convention-B test ============
    float mrowD[6], w_t = 0.f, areg = 0.f;
    int jlo = 0;
    #pragma unroll
    for (int k = 0; k < 6; k++) mrowD[k] = 0.f;
    if (t < NTOK) {
        jlo = (t > 12) ? ((t - 12) >> 2) : 0;
        float pa = __fmul_rn((float)(t + 1), INV100);
        float kv[6];
        float r = 0.f;
        #pragma unroll
        for (int k = 0; k < 6; k++) {
            int j = jlo + k;
            float kvv = 0.f;
            if (j <= 24) {
                float pb = __fmul_rn((float)(j + 1), INV25);
                if (fabsf(__fsub_rn(pa, pb)) < 0.1f) {
                    float dot = 0.f;
                    const float* wj = &otw[j * 32];
                    #pragma unroll
                    for (int d = 0; d < 32; d++) dot += y[d] * wj[d];
                    kvv = __fdiv_rn(dot, 0.1f);
                }
            }
            kv[k] = kvv;
            r = fmaxf(r, kvv);
        }
        w_t = __expf(-r);
        #pragma unroll
        for (int k = 0; k < 6; k++)
            mrowD[k] = __expf(kv[k] - r) - w_t;   // exactly 0 when kv==0
        #pragma unroll
        for (int j = 0; j < MP; j++) KmG[(t + 8) * MP + j] = 0.f;
        #pragma unroll
        for (int k = 0; k < 6; k++) {
            int j = jlo + k;
            if (j <= 24) KmG[(t + 8) * MP + j] = mrowD[k];
        }
        areg = (aaArr[t] != 0.0f) ? (*cntp) : 0.f;
    } else {
        // guard rows: tids 100..107 -> rows 0..7; tids 108..121 -> rows 108..121
        int gr = (t < 108) ? (t - 100) : t;
        if (t < 122)
            for (int j = 0; j < MP; j++) KmG[gr * MP + j] = 0.f;
    }
    if (tid < 32) vv[tid] = (tid < OTM) ? 1.0f : 0.0f;
    __syncthreads();

    // ================= Band-sparse linear Sinkhorn w/ bitwise early exit ==========
    {
        const int j = (t < NTOK) ? (t >> 2) : 24;
        const int sg = t & 3;
        int done = 0;
        for (int chunk = 0; chunk < 10 && !done; chunk++) {
            float vprev = 0.f;
            if (sg == 0 && t < NTOK) vprev = vv[j];
            for (int it = 0; it < 10; it++) {
                float xv = vv[lane];
                xv += __shfl_xor_sync(0xffffffffu, xv, 16);
                xv += __shfl_xor_sync(0xffffffffu, xv, 8);
                xv += __shfl_xor_sync(0xffffffffu, xv, 4);
                xv += __shfl_xor_sync(0xffffffffu, xv, 2);
                xv += __shfl_xor_sync(0xffffffffu, xv, 1);
                if (t < NTOK) {
                    float sacc = w_t * xv;
                    #pragma unroll
                    for (int k = 0; k < 6; k++) sacc += mrowD[k] * vv[jlo + k];
                    float u = areg / sacc;
                    uuG[t + 8] = u;
                    wu[t] = w_t * u;
                }
                __syncthreads();
                float sv = wu[lane] + wu[lane + 32] + wu[lane + 64]
                         + ((lane < 4) ? wu[lane + 96] : 0.f);
                sv += __shfl_xor_sync(0xffffffffu, sv, 16);
                sv += __shfl_xor_sync(0xffffffffu, sv, 8);
                sv += __shfl_xor_sync(0xffffffffu, sv, 4);
                sv += __shfl_xor_sync(0xffffffffu, sv, 2);
                sv += __shfl_xor_sync(0xffffffffu, sv, 1);
                // column partials: rows 4j+k (guard rows exact zeros -> unconditional)
                float sacc = 0.f;
                #pragma unroll
                for (int k = sg; k < 23; k += 4)
                    sacc += KmG[(4 * j + k) * MP + j] * uuG[4 * j + k];
                sacc += __shfl_xor_sync(0xffffffffu, sacc, 1);
                sacc += __shfl_xor_sync(0xffffffffu, sacc, 2);
                if (sg == 0 && t < NTOK) vv[j] = 0.04f / (sv + sacc);
                __syncthreads();
            }
            if (tid == 0) *flagp = 0;
            __syncthreads();
            if (sg == 0 && t < NTOK && vv[j] != vprev) *flagp = 1;
            __syncthreads();
            if (*flagp == 0) done = 1;
        }
    }

    // Fold u into D band
    if (t < NTOK) {
        float u = uuG[t + 8];
        #pragma unroll
        for (int k = 0; k < 6; k++) {
            int j = jlo + k;
            if (j <= 24) KmG[(t + 8) * MP + j] = mrowD[k] * u;
        }
    }
    __syncthreads();
    // Pd[d] = sum_i wu_i * Y[i][d]
    if (tid < 32) {
        float acc = 0.f;
        for (int i = 0; i < NTOK; i++) acc += wu[i] * YbG[(i + 8) * YP + tid];
        Pd[tid] = acc;
    }
    __syncthreads();

    // ================= Output (guard rows make loop unconditional) =================
    for (int idx = tid; idx < OTM * 32; idx += NTHREADS) {
        int m = idx >> 5, d = idx & 31;
        float acc = 0.f;
        #pragma unroll
        for (int k = 0; k < 23; k++)
            acc += KmG[(4 * m + k) * MP + m] * YbG[(4 * m + k) * YP + d];
        out[((size_t)s * OTM + m) * 32 + d] = (Pd[d] + acc) * (25.0f * vv[m]);
    }
}

extern "C" void kernel_launch(void* const* d_in, const int* in_sizes, int n_in,
                              void* d_out, int out_size)
{
    (void)in_sizes; (void)n_in; (void)out_size;
    const float* jc    = (const float*)d_in[0];
    const int*   flg   = (const int*)  d_in[1];
    const float* enc_w = (const float*)d_in[2];
    const float* enc_b = (const float*)d_in[3];
    const float* B_sig = (const float*)d_in[4];
    const float* B_jid = (const float*)d_in[5];
    const float* qkv_w = (const float*)d_in[6];
    const float* out_w = (const float*)d_in[7];
    const float* out_b = (const float*)d_in[8];
    const float* ln1_s = (const float*)d_in[9];
    const float* ln1_b = (const float*)d_in[10];
    const float* ln2_s = (const float*)d_in[11];
    const float* ln2_b = (const float*)d_in[12];
    const float* ff1_w = (const float*)d_in[13];
    const float* ff1_b = (const float*)d_in[14];
    const float* ff2_w = (const float*)d_in[15];
    const float* ff2_b = (const float*)d_in[16];
    const float* dec_w = (const float*)d_in[17];
    const float* dec_b = (const float*)d_in[18];
    const float* ot_w  = (const float*)d_in[19];
    float* out = (float*)d_out;

    cudaFuncSetAttribute(jc_struc_kernel,
                         cudaFuncAttributeMaxDynamicSharedMemorySize, SMEM_BYTES);
    jc_struc_kernel<<<800, NTHREADS, SMEM_BYTES>>>(
        jc, flg, enc_w, enc_b, B_sig, B_jid, qkv_w, out_w, out_b,
        ln1_s, ln1_b, ln2_s, ln2_b, ff1_w, ff1_b, ff2_w, ff2_b,
        dec_w, dec_b, ot_w, out);
}

// round 13
// speedup vs baseline: 1.0846x; 1.0846x over previous
#include <cuda_runtime.h>
#include <math.h>

#define NTOK 100
#define OTM  25
#define MP   26
#define QP   18
#define YP   33
#define NTHREADS 128

// smem layout (float units), 9284 floats = 37136 B
#define OFF_W    0        // wbuf[2704]; after decoder: YbG rows 0..118 (row=i+8)
#define OFF_QKV  3952     // QKV[100][18]=1800; after transformer: otw[800], Pd[32]@+800
#define OFF_KM   5752     // KmG[122][26]=3172 (row=i+8); vlist aliases during transformer
#define OFF_UU   8924     // uuG[124] (idx=i+8)
#define OFF_WU   9048     // wu[100]
#define OFF_VV   9148     // vv[32] ([25..31]=0)
#define OFF_AA   9180     // aaArr[100]
#define OFF_NV   9280
#define OFF_CNT  9281
#define OFF_FLG  9282
#define SMEM_FLOATS 9284
#define SMEM_BYTES  (SMEM_FLOATS * 4)

__global__ void __launch_bounds__(NTHREADS, 4)
jc_struc_kernel(const float* __restrict__ jc,   const int* __restrict__ flg,
                const float* __restrict__ enc_w, const float* __restrict__ enc_b,
                const float* __restrict__ B_sig, const float* __restrict__ B_jid,
                const float* __restrict__ qkv_w, const float* __restrict__ out_w,
                const float* __restrict__ out_b, const float* __restrict__ ln1_s,
                const float* __restrict__ ln1_b, const float* __restrict__ ln2_s,
                const float* __restrict__ ln2_b, const float* __restrict__ ff1_w,
                const float* __restrict__ ff1_b, const float* __restrict__ ff2_w,
                const float* __restrict__ ff2_b, const float* __restrict__ dec_w,
                const float* __restrict__ dec_b, const float* __restrict__ ot_w,
                float* __restrict__ out)
{
    extern __shared__ float sm[];
    float* wbuf  = sm + OFF_W;
    float* YbG   = sm + OFF_W;                 // row = i+8, pitch 33
    float* SQ    = sm + OFF_QKV;
    float* otw   = sm + OFF_QKV;
    float* Pd    = sm + OFF_QKV + 800;
    float* KmG   = sm + OFF_KM;                // row = i+8, pitch 26
    int*   vlist = (int*)(sm + OFF_KM);
    float* uuG   = sm + OFF_UU;                // idx = i+8
    float* wu    = sm + OFF_WU;
    float* vv    = sm + OFF_VV;
    float* aaArr = sm + OFF_AA;
    int*   nvp   = (int*)(sm + OFF_NV);
    float* cntp  = sm + OFF_CNT;
    int*   flagp = (int*)(sm + OFF_FLG);

    const int tid  = threadIdx.x;
    const int lane = tid & 31;
    const int s    = blockIdx.x;
    const int t    = tid;
    const float TWO_PI = 6.283185307179586f;
    const float INV_SQRT2 = 0.7071067811865476f;
    const float INV100 = 0.00999999977648258209228515625f; // fl32(1/100)
    const float INV25  = 0.039999999105930328369140625f;   // fl32(1/25)

    float x[64];

    // ================= Stage embedding constants, then embed =================
    for (int i = tid; i < 384; i += NTHREADS) {
        float v;
        if (i < 96)       v = B_sig[i];
        else if (i < 128) v = B_jid[i - 96];
        else if (i < 320) v = enc_w[i - 128];
        else              v = enc_b[i - 320];
        wbuf[i] = v;
    }
    __syncthreads();
    if (t < NTOK) {
        const size_t base = ((size_t)s * NTOK + t) * 3;
        const float p0 = jc[base + 0], p1 = jc[base + 1], p2 = jc[base + 2];
        const float jd = (float)(t / 4);
        aaArr[t] = (flg[(size_t)s * NTOK + t] > 0) ? 1.0f : 0.0f;
        const float* bs = wbuf;
        const float* bj = wbuf + 96;
        const float* ew = wbuf + 128;
        const float* eb = wbuf + 320;
        #pragma unroll 4
        for (int c = 0; c < 32; c++) {
            float proj = TWO_PI * (p0 * bs[c] + p1 * bs[32 + c] + p2 * bs[64 + c]);
            float ss, cs; __sincosf(proj, &ss, &cs);
            float pj = TWO_PI * (jd * bj[c]);
            float sj, cj; __sincosf(pj, &sj, &cj);
            x[c]      = (p0 * ew[c]      + p1 * ew[64 + c]      + p2 * ew[128 + c])      + eb[c]      + ss + sj;
            x[c + 32] = (p0 * ew[c + 32] + p1 * ew[64 + c + 32] + p2 * ew[128 + c + 32]) + eb[c + 32] + cs + cj;
        }
    }
    __syncthreads();
    if (tid == 0) {
        int c = 0;
        for (int i = 0; i < NTOK; i++) {
            if (aaArr[i] != 0.0f) vlist[c++] = i;
        }
        *nvp = c;
        *cntp = 1.0f / (float)c;
    }
    __syncthreads();
    const int nv = *nvp;

    // ================= Transformer layers =================
    #pragma unroll 1
    for (int l = 0; l < 4; l++) {
        // Phase A: ln1_s@0, ln1_b@64, qkv padded [64][20] @128
        for (int i = tid; i < 1408; i += NTHREADS) {
            float v;
            if (i < 64)       v = ln1_s[l * 64 + i];
            else if (i < 128) v = ln1_b[l * 64 + (i - 64)];
            else {
                int k = (i - 128) / 20, c = (i - 128) % 20;
                v = (c < 18) ? qkv_w[(l * 64 + k) * 18 + c] : 0.0f;
            }
            wbuf[i] = v;
        }
        __syncthreads();

        // LN1 (regs) + QKV matmul (float4 weights, scalar FMA)
        if (t < NTOK) {
            float ssum = 0.f, sq = 0.f;
            #pragma unroll
            for (int d = 0; d < 64; d++) { float v = x[d]; ssum += v; sq += v * v; }
            float mu = ssum * (1.0f / 64.0f);
            float rs = rsqrtf(sq * (1.0f / 64.0f) - mu * mu + 1e-5f);

            float acc[18];
            #pragma unroll
            for (int c = 0; c < 18; c++) acc[c] = 0.f;
            #pragma unroll
            for (int k = 0; k < 64; k++) {
                float h = fmaf((x[k] - mu) * rs, wbuf[k], wbuf[64 + k]);
                const float4* wr = (const float4*)&wbuf[128 + k * 20];
                float4 w0 = wr[0], w1 = wr[1], w2 = wr[2], w3 = wr[3], w4 = wr[4];
                acc[0] += h * w0.x;  acc[1] += h * w0.y;  acc[2] += h * w0.z;  acc[3] += h * w0.w;
                acc[4] += h * w1.x;  acc[5] += h * w1.y;  acc[6] += h * w1.z;  acc[7] += h * w1.w;
                acc[8] += h * w2.x;  acc[9] += h * w2.y;  acc[10] += h * w2.z; acc[11] += h * w2.w;
                acc[12] += h * w3.x; acc[13] += h * w3.y; acc[14] += h * w3.z; acc[15] += h * w3.w;
                acc[16] += h * w4.x; acc[17] += h * w4.y;
            }
            float* q = &SQ[t * QP];
            *(float2*)(q + 0)  = make_float2(acc[0], acc[1]);
            *(float2*)(q + 2)  = make_float2(acc[2], acc[3]);
            *(float2*)(q + 4)  = make_float2(acc[4], acc[5]);
            *(float2*)(q + 6)  = make_float2(acc[6] * INV_SQRT2, acc[7] * INV_SQRT2);
            *(float2*)(q + 8)  = make_float2(acc[8] * INV_SQRT2, acc[9] * INV_SQRT2);
            *(float2*)(q + 10) = make_float2(acc[10] * INV_SQRT2, acc[11] * INV_SQRT2);
            *(float2*)(q + 12) = make_float2(acc[12], acc[13]);
            *(float2*)(q + 14) = make_float2(acc[14], acc[15]);
            *(float2*)(q + 16) = make_float2(acc[16], acc[17]);
        }
        __syncthreads();

        // Phase B+C weights — all threads, cooperative (R10 scheme)
        for (int i = tid; i < 576; i += NTHREADS) {
            float v;
            if (i < 384)      v = out_w[l * 384 + i];
            else if (i < 448) v = out_b[l * 64 + (i - 384)];
            else if (i < 512) v = ln2_s[l * 64 + (i - 448)];
            else              v = ln2_b[l * 64 + (i - 512)];
            wbuf[i] = v;
        }
        for (int i = tid; i < 256; i += NTHREADS)
            ((float4*)&wbuf[576])[i] = ((const float4*)&ff1_w[l * 1024])[i];
        for (int i = tid; i < 16; i += NTHREADS)
            wbuf[1600 + i] = ff1_b[l * 16 + i];
        for (int i = tid; i < 256; i += NTHREADS)
            ((float4*)&wbuf[1616])[i] = ((const float4*)&ff2_w[l * 1024])[i];
        for (int i = tid; i < 64; i += NTHREADS)
            wbuf[2640 + i] = ff2_b[l * 64 + i];

        // Attention: online softmax over compacted valid keys
        float o[6];
        if (t < NTOK) {
            const float* qp = &SQ[t * QP];
            float q0 = qp[0], q1 = qp[1], q2 = qp[2], q3 = qp[3], q4 = qp[4], q5 = qp[5];
            float m0 = -3.0e38f, m1 = -3.0e38f, m2 = -3.0e38f;
            float d0 = 0.f, d1 = 0.f, d2 = 0.f;
            float a0 = 0.f, a1 = 0.f, a2 = 0.f, a3 = 0.f, a4 = 0.f, a5 = 0.f;
            for (int jj = 0; jj < nv; jj++) {
                int j = vlist[jj];
                const float* kj = &SQ[j * QP];
                float2 k01 = *(const float2*)(kj + 6);
                float2 k23 = *(const float2*)(kj + 8);
                float2 k45 = *(const float2*)(kj + 10);
                float2 v01 = *(const float2*)(kj + 12);
                float2 v23 = *(const float2*)(kj + 14);
                float2 v45 = *(const float2*)(kj + 16);
                float s0 = q0 * k01.x + q1 * k01.y;
                float s1 = q2 * k23.x + q3 * k23.y;
                float s2 = q4 * k45.x + q5 * k45.y;
                if (s0 <= m0 && s1 <= m1 && s2 <= m2) {
                    float e0 = __expf(s0 - m0), e1 = __expf(s1 - m1), e2 = __expf(s2 - m2);
                    d0 += e0; a0 += e0 * v01.x; a1 += e0 * v01.y;
                    d1 += e1; a2 += e1 * v23.x; a3 += e1 * v23.y;
                    d2 += e2; a4 += e2 * v45.x; a5 += e2 * v45.y;
                } else {
                    float n0 = fmaxf(m0, s0), r0 = __expf(m0 - n0), e0 = __expf(s0 - n0);
                    d0 = d0 * r0 + e0; a0 = a0 * r0 + e0 * v01.x; a1 = a1 * r0 + e0 * v01.y; m0 = n0;
                    float n1 = fmaxf(m1, s1), r1 = __expf(m1 - n1), e1 = __expf(s1 - n1);
                    d1 = d1 * r1 + e1; a2 = a2 * r1 + e1 * v23.x; a3 = a3 * r1 + e1 * v23.y; m1 = n1;
                    float n2 = fmaxf(m2, s2), r2 = __expf(m2 - n2), e2 = __expf(s2 - n2);
                    d2 = d2 * r2 + e2; a4 = a4 * r2 + e2 * v45.x; a5 = a5 * r2 + e2 * v45.y; m2 = n2;
                }
            }
            o[0] = a0 / d0; o[1] = a1 / d0;
            o[2] = a2 / d1; o[3] = a3 / d1;
            o[4] = a4 / d2; o[5] = a5 / d2;
        }
        __syncthreads();

        if (t < NTOK) {
            // out projection + residual
            #pragma unroll
            for (int eh = 0; eh < 4; eh++) {
                const int e0 = eh * 16;
                float acc[16];
                const float4* bb = (const float4*)&wbuf[384 + e0];
                #pragma unroll
                for (int i = 0; i < 4; i++) {
                    float4 b4 = bb[i];
                    acc[4*i] = b4.x; acc[4*i+1] = b4.y; acc[4*i+2] = b4.z; acc[4*i+3] = b4.w;
                }
                #pragma unroll
                for (int c = 0; c < 6; c++) {
                    float oc = o[c];
                    const float4* wr = (const float4*)&wbuf[c * 64 + e0];
                    #pragma unroll
                    for (int i = 0; i < 4; i++) {
                        float4 w4 = wr[i];
                        acc[4*i]   += oc * w4.x; acc[4*i+1] += oc * w4.y;
                        acc[4*i+2] += oc * w4.z; acc[4*i+3] += oc * w4.w;
                    }
                }
                #pragma unroll
                for (int i = 0; i < 16; i++) x[e0 + i] += acc[i];
            }
            // LN2 stats
            float ssum = 0.f, sq = 0.f;
            #pragma unroll
            for (int d = 0; d < 64; d++) { float v = x[d]; ssum += v; sq += v * v; }
            float mu = ssum * (1.0f / 64.0f);
            float rs = rsqrtf(sq * (1.0f / 64.0f) - mu * mu + 1e-5f);
            // FF1 (LN2 inline)
            float g[16];
            {
                const float4* bb = (const float4*)&wbuf[1600];
                #pragma unroll
                for (int i = 0; i < 4; i++) {
                    float4 b4 = bb[i];
                    g[4*i] = b4.x; g[4*i+1] = b4.y; g[4*i+2] = b4.z; g[4*i+3] = b4.w;
                }
            }
            #pragma unroll
            for (int k = 0; k < 64; k++) {
                float h = fmaf((x[k] - mu) * rs, wbuf[448 + k], wbuf[512 + k]);
                const float4* wr = (const float4*)&wbuf[576 + k * 16];
                float4 w0 = wr[0], w1 = wr[1], w2 = wr[2], w3 = wr[3];
                g[0] += h * w0.x;  g[1] += h * w0.y;  g[2] += h * w0.z;  g[3] += h * w0.w;
                g[4] += h * w1.x;  g[5] += h * w1.y;  g[6] += h * w1.z;  g[7] += h * w1.w;
                g[8] += h * w2.x;  g[9] += h * w2.y;  g[10] += h * w2.z; g[11] += h * w2.w;
                g[12] += h * w3.x; g[13] += h * w3.y; g[14] += h * w3.z; g[15] += h * w3.w;
            }
            #pragma unroll
            for (int c = 0; c < 16; c++)
                g[c] = 0.5f * g[c] * (1.0f + erff(g[c] * INV_SQRT2));
            // FF2 + residual
            #pragma unroll
            for (int eh = 0; eh < 4; eh++) {
                const int e0 = eh * 16;
                float acc[16];
                const float4* bb = (const float4*)&wbuf[2640 + e0];
                #pragma unroll
                for (int i = 0; i < 4; i++) {
                    float4 b4 = bb[i];
                    acc[4*i] = b4.x; acc[4*i+1] = b4.y; acc[4*i+2] = b4.z; acc[4*i+3] = b4.w;
                }
                #pragma unroll
                for (int c = 0; c < 16; c++) {
                    float gc = g[c];
                    const float4* wr = (const float4*)&wbuf[1616 + c * 64 + e0];
                    #pragma unroll
                    for (int i = 0; i < 4; i++) {
                        float4 w4 = wr[i];
                        acc[4*i]   += gc * w4.x; acc[4*i+1] += gc * w4.y;
                        acc[4*i+2] += gc * w4.z; acc[4*i+3] += gc * w4.w;
                    }
                }
                #pragma unroll
                for (int i = 0; i < 16; i++) x[e0 + i] += acc[i];
            }
        }
        __syncthreads();
    }

    // ================= Decoder weights + otw =================
    for (int i = tid; i < 512; i += NTHREADS)
        ((float4*)&wbuf[0])[i] = ((const float4*)dec_w)[i];
    for (int i = tid; i < 32; i += NTHREADS)
        wbuf[2048 + i] = dec_b[i];
    for (int i = tid; i < 200; i += NTHREADS)
        ((float4*)otw)[i] = ((const float4*)ot_w)[i];
    __syncthreads();

    // ================= Decoder -> y regs =================
    float y[32];
    if (t < NTOK) {
        const float4* bb = (const float4*)&wbuf[2048];
        #pragma unroll
        for (int i = 0; i < 8; i++) {
            float4 b4 = bb[i];
            y[4*i] = b4.x; y[4*i+1] = b4.y; y[4*i+2] = b4.z; y[4*i+3] = b4.w;
        }
        #pragma unroll
        for (int k = 0; k < 64; k++) {
            float xv = x[k];
            const float4* wr = (const float4*)&wbuf[k * 32];
            #pragma unroll
            for (int i = 0; i < 8; i++) {
                float4 w4 = wr[i];
                y[4*i]   += xv * w4.x; y[4*i+1] += xv * w4.y;
                y[4*i+2] += xv * w4.z; y[4*i+3] += xv * w4.w;
            }
        }
        #pragma unroll
        for (int c = 0; c < 32; c++) y[c] = fmaxf(y[c], 0.f);
    }
    __syncthreads();        // decoder-weight reads done; YbG may overwrite wbuf
    if (t < NTOK) {
        #pragma unroll
        for (int c = 0; c < 32; c++) YbG[(t + 8) * YP + c] = y[c];
    }
    // zero guard rows of YbG (rows 0..7, 108..118) and uuG guards
    for (int i = tid; i < 264; i += NTHREADS) YbG[i] = 0.f;
    for (int i = tid; i < 363; i += NTHREADS) YbG[108 * YP + i] = 0.f;
    if (tid < 8) uuG[tid] = 0.f;
    if (tid >= 108 && tid < 124) uuG[tid] = 0.f;

    // ================= K-build: band window, exact convention-B test ============
    float mrowD[6], w_t = 0.f, areg = 0.f;
    int jlo = 0;
    #pragma unroll
    for (int k = 0; k < 6; k++) mrowD[k] = 0.f;
    if (t < NTOK) {
        jlo = (t > 12) ? ((t - 12) >> 2) : 0;
        float pa = __fmul_rn((float)(t + 1), INV100);
        float kv[6];
        float r = 0.f;
        #pragma unroll
        for (int k = 0; k < 6; k++) {
            int j = jlo + k;
            float kvv = 0.f;
            if (j <= 24) {
                float pb = __fmul_rn((float)(j + 1), INV25);
                if (fabsf(__fsub_rn(pa, pb)) < 0.1f) {
                    float dot = 0.f;
                    const float* wj = &otw[j * 32];
                    #pragma unroll
                    for (int d = 0; d < 32; d++) dot += y[d] * wj[d];
                    kvv = __fdiv_rn(dot, 0.1f);
                }
            }
            kv[k] = kvv;
            r = fmaxf(r, kvv);
        }
        w_t = __expf(-r);
        #pragma unroll
        for (int k = 0; k < 6; k++)
            mrowD[k] = __expf(kv[k] - r) - w_t;   // exactly 0 when kv==0
        #pragma unroll
        for (int j = 0; j < MP; j++) KmG[(t + 8) * MP + j] = 0.f;
        #pragma unroll
        for (int k = 0; k < 6; k++) {
            int j = jlo + k;
            if (j <= 24) KmG[(t + 8) * MP + j] = mrowD[k];
        }
        areg = (aaArr[t] != 0.0f) ? (*cntp) : 0.f;
    } else {
        // guard rows: tids 100..107 -> rows 0..7; tids 108..121 -> rows 108..121
        int gr = (t < 108) ? (t - 100) : t;
        if (t < 122)
            for (int j = 0; j < MP; j++) KmG[gr * MP + j] = 0.f;
    }
    if (tid < 32) vv[tid] = (tid < OTM) ? 1.0f : 0.0f;
    __syncthreads();

    // ================= Band-sparse linear Sinkhorn w/ bitwise early exit ==========
    {
        const int j = (t < NTOK) ? (t >> 2) : 24;
        const int sg = t & 3;
        int done = 0;
        for (int chunk = 0; chunk < 10 && !done; chunk++) {
            float vprev = 0.f;
            if (sg == 0 && t < NTOK) vprev = vv[j];
            for (int it = 0; it < 10; it++) {
                float xv = vv[lane];
                xv += __shfl_xor_sync(0xffffffffu, xv, 16);
                xv += __shfl_xor_sync(0xffffffffu, xv, 8);
                xv += __shfl_xor_sync(0xffffffffu, xv, 4);
                xv += __shfl_xor_sync(0xffffffffu, xv, 2);
                xv += __shfl_xor_sync(0xffffffffu, xv, 1);
                if (t < NTOK) {
                    float sacc = w_t * xv;
                    #pragma unroll
                    for (int k = 0; k < 6; k++) sacc += mrowD[k] * vv[jlo + k];
                    float u = areg / sacc;
                    uuG[t + 8] = u;
                    wu[t] = w_t * u;
                }
                __syncthreads();
                float sv = wu[lane] + wu[lane + 32] + wu[lane + 64]
                         + ((lane < 4) ? wu[lane + 96] : 0.f);
                sv += __shfl_xor_sync(0xffffffffu, sv, 16);
                sv += __shfl_xor_sync(0xffffffffu, sv, 8);
                sv += __shfl_xor_sync(0xffffffffu, sv, 4);
                sv += __shfl_xor_sync(0xffffffffu, sv, 2);
                sv += __shfl_xor_sync(0xffffffffu, sv, 1);
                // column partials: rows 4j+k (guard rows exact zeros -> unconditional)
                float sacc = 0.f;
                #pragma unroll
                for (int k = sg; k < 23; k += 4)
                    sacc += KmG[(4 * j + k) * MP + j] * uuG[4 * j + k];
                sacc += __shfl_xor_sync(0xffffffffu, sacc, 1);
                sacc += __shfl_xor_sync(0xffffffffu, sacc, 2);
                if (sg == 0 && t < NTOK) vv[j] = 0.04f / (sv + sacc);
                __syncthreads();
            }
            if (tid == 0) *flagp = 0;
            __syncthreads();
            if (sg == 0 && t < NTOK && vv[j] != vprev) *flagp = 1;
            __syncthreads();
            if (*flagp == 0) done = 1;
        }
    }

    // Fold u into D band
    if (t < NTOK) {
        float u = uuG[t + 8];
        #pragma unroll
        for (int k = 0; k < 6; k++) {
            int j = jlo + k;
            if (j <= 24) KmG[(t + 8) * MP + j] = mrowD[k] * u;
        }
    }
    __syncthreads();
    // Pd[d] = sum_i wu_i * Y[i][d]
    if (tid < 32) {
        float acc = 0.f;
        for (int i = 0; i < NTOK; i++) acc += wu[i] * YbG[(i + 8) * YP + tid];
        Pd[tid] = acc;
    }
    __syncthreads();

    // ================= Output (guard rows make loop unconditional) =================
    for (int idx = tid; idx < OTM * 32; idx += NTHREADS) {
        int m = idx >> 5, d = idx & 31;
        float acc = 0.f;
        #pragma unroll
        for (int k = 0; k < 23; k++)
            acc += KmG[(4 * m + k) * MP + m] * YbG[(4 * m + k) * YP + d];
        out[((size_t)s * OTM + m) * 32 + d] = (Pd[d] + acc) * (25.0f * vv[m]);
    }
}

extern "C" void kernel_launch(void* const* d_in, const int* in_sizes, int n_in,
                              void* d_out, int out_size)
{
    (void)in_sizes; (void)n_in; (void)out_size;
    const float* jc    = (const float*)d_in[0];
    const int*   flg   = (const int*)  d_in[1];
    const float* enc_w = (const float*)d_in[2];
    const float* enc_b = (const float*)d_in[3];
    const float* B_sig = (const float*)d_in[4];
    const float* B_jid = (const float*)d_in[5];
    const float* qkv_w = (const float*)d_in[6];
    const float* out_w = (const float*)d_in[7];
    const float* out_b = (const float*)d_in[8];
    const float* ln1_s = (const float*)d_in[9];
    const float* ln1_b = (const float*)d_in[10];
    const float* ln2_s = (const float*)d_in[11];
    const float* ln2_b = (const float*)d_in[12];
    const float* ff1_w = (const float*)d_in[13];
    const float* ff1_b = (const float*)d_in[14];
    const float* ff2_w = (const float*)d_in[15];
    const float* ff2_b = (const float*)d_in[16];
    const float* dec_w = (const float*)d_in[17];
    const float* dec_b = (const float*)d_in[18];
    const float* ot_w  = (const float*)d_in[19];
    float* out = (float*)d_out;

    cudaFuncSetAttribute(jc_struc_kernel,
                         cudaFuncAttributeMaxDynamicSharedMemorySize, SMEM_BYTES);
    jc_struc_kernel<<<800, NTHREADS, SMEM_BYTES>>>(
        jc, flg, enc_w, enc_b, B_sig, B_jid, qkv_w, out_w, out_b,
        ln1_s, ln1_b, ln2_s, ln2_b, ff1_w, ff1_b, ff2_w, ff2_b,
        dec_w, dec_b, ot_w, out);
}